// round 10
// baseline (speedup 1.0000x reference)
#include <cuda_runtime.h>
#include <stdint.h>
#include <math.h>

// Problem shapes (fixed for this dataset entry)
#define B_    16
#define CH    512
#define HW    16384
#define C_    16              // selected classes
#define G_    32              // groups (CH/C_)
#define NP    120             // off-diagonal pairs
#define HNP   60              // pairs per thread-half
#define S_    4               // HW chunks per (b,g)
#define CHUNK (HW/S_)         // 4096
#define NBG   (B_*G_)         // 512
#define NITEMS (NBG*S_)       // 2048
#define THREADS 256
#define GRID_GRAM 296         // persistent: 2 CTAs per SM

// Scratch (static __device__ — no allocations allowed)
__device__ int   d_src[CH];              // [k*C_+cls] -> source channel in x
__device__ float d_wgh[CH];              // [k*C_+cls] -> sigmoid(|w|)
__device__ float d_part[NITEMS*NP];      // partial Gram sums

// ---------------------------------------------------------------------------
// Kernel 1: rank-based top-G selection, 8-way parallel per class.
// rank(c) = #{d : |w_d|>|w_c| || (|w_d|==|w_c| && d<c)} == stable argsort pos.
// ---------------------------------------------------------------------------
__global__ void z_prep_kernel(const float* __restrict__ cw, const int* __restrict__ sel) {
    __shared__ unsigned int sbits[CH];
    __shared__ int part[64][8];
    int t = threadIdx.x;
    int cls_idx = blockIdx.x >> 3;        // 0..15
    int co      = blockIdx.x & 7;         // channel octant
    int cls = sel[cls_idx];

    sbits[t] = __float_as_uint(fabsf(cw[cls*CH + t]));
    __syncthreads();

    int c = co*64 + (t >> 3);             // channel this thread helps rank
    int p = t & 7;                        // d-slice
    unsigned int mine = sbits[c];
    int cnt = 0;
#pragma unroll 8
    for (int dd = p*64; dd < p*64 + 64; dd++) {
        unsigned int o = sbits[dd];
        cnt += (o > mine) || (o == mine && dd < c);
    }
    part[t >> 3][p] = cnt;
    __syncthreads();

    if (t < 64) {
        int ch = co*64 + t;
        int rank = part[t][0]+part[t][1]+part[t][2]+part[t][3]
                 + part[t][4]+part[t][5]+part[t][6]+part[t][7];
        if (rank < G_) {
            float val = __uint_as_float(sbits[ch]);
            d_src[rank*C_ + cls_idx] = ch;
            d_wgh[rank*C_ + cls_idx] = 1.0f / (1.0f + expf(-val));
        }
    }
}

// Dummy no-op kernels: keep gram at launch #4 (the ncu capture slot).
__global__ void y_dummy1_kernel() {}
__global__ void y_dummy2_kernel() {}

// ---------------------------------------------------------------------------
// Scalar accumulate of pairs [QLO, QLO+60) for one float2 per channel.
// ---------------------------------------------------------------------------
template<int QLO>
__device__ __forceinline__ void accum60(float* __restrict__ acc,
                                        const float2* __restrict__ v) {
    int q = 0;
#pragma unroll
    for (int i = 0; i < C_; i++) {
#pragma unroll
        for (int j = i+1; j < C_; j++) {
            if (q >= QLO && q < QLO + HNP) {
                acc[q - QLO] += v[i].x * v[j].x;
                acc[q - QLO] += v[i].y * v[j].y;
            }
            q++;
        }
    }
}

// ---------------------------------------------------------------------------
// Kernel 2: partial Gram, persistent (2 CTAs/SM). In-CTA pair split: warps
// 0-3 accumulate pairs 0..59, warps 4-7 pairs 60..119 over IDENTICAL
// positions, so the second half's loads hit L1 (same SM) — DRAM request
// count stays 1x (unlike the failed cross-SM twin split). 60 accumulators +
// 16 float2 loads ≈ 115 regs -> 2 CTAs/SM, 16 warps, no spills.
// ---------------------------------------------------------------------------
__global__ void __launch_bounds__(THREADS, 2)
a0_gram_kernel(const float* __restrict__ x) {
    int t    = threadIdx.x;
    int half = t >> 7;                    // 0: pairs 0..59, 1: pairs 60..119
    int kt   = t & 127;
    __shared__ int soff[C_];
    __shared__ float red[THREADS/32][HNP];

    for (int item = blockIdx.x; item < NITEMS; item += GRID_GRAM) {
        int bg = item >> 2;               // S_ == 4
        int s  = item & 3;
        int b  = bg / G_;
        int g  = bg % G_;

        if (t < C_)
            soff[t] = d_src[g*C_ + t] * (HW/2);  // channel offset in float2 units
        __syncthreads();

        const float2* base = (const float2*)x + ((size_t)b * CH) * (HW/2) + (size_t)s * (CHUNK/2);
        int off[C_];
#pragma unroll
        for (int i = 0; i < C_; i++) off[i] = soff[i];

        float acc[HNP];
#pragma unroll
        for (int q = 0; q < HNP; q++) acc[q] = 0.0f;

        // both halves sweep the same 2048 float2 positions (stride 128)
        for (int it = kt; it < CHUNK/2; it += 128) {
            float2 v[C_];
#pragma unroll
            for (int i = 0; i < C_; i++) v[i] = base[off[i] + it];
            if (half == 0) accum60<0>(acc, v);
            else           accum60<HNP>(acc, v);
        }

        // warp reduce all 60 accumulators
#pragma unroll
        for (int q = 0; q < HNP; q++) {
            float a = acc[q];
#pragma unroll
            for (int o = 16; o > 0; o >>= 1)
                a += __shfl_down_sync(0xffffffffu, a, o);
            acc[q] = a;
        }

        int warp = t >> 5, lane = t & 31;
        if (lane == 0) {
#pragma unroll
            for (int q = 0; q < HNP; q++) red[warp][q] = acc[q];
        }
        __syncthreads();
        if (t < HNP) {                        // combine half0 (warps 0..3)
            float sum = red[0][t] + red[1][t] + red[2][t] + red[3][t];
            d_part[(size_t)item*NP + t] = sum;
        } else if (t >= 64 && t < 64 + HNP) { // combine half1 (warps 4..7)
            int p = t - 64;
            float sum = red[4][p] + red[5][p] + red[6][p] + red[7][p];
            d_part[(size_t)item*NP + HNP + p] = sum;
        }
        __syncthreads();                  // smem reuse safety for next item
    }
}

// ---------------------------------------------------------------------------
// Kernel 3: fused combine + |.|*w_i*w_j + full reduction + normalization.
// One CTA, 512 threads: thread t owns (b,g)=t; sums S_=4 chunks per pair.
// ---------------------------------------------------------------------------
__global__ void reduce_kernel(float* __restrict__ out) {
    int bg = threadIdx.x;                 // 0..NBG-1
    int g  = bg % G_;
    const float* p0 = d_part + (size_t)(bg*S_ + 0) * NP;
    const float* p1 = d_part + (size_t)(bg*S_ + 1) * NP;
    const float* p2 = d_part + (size_t)(bg*S_ + 2) * NP;
    const float* p3 = d_part + (size_t)(bg*S_ + 3) * NP;

    float w[C_];
#pragma unroll
    for (int i = 0; i < C_; i++) w[i] = d_wgh[g*C_ + i];

    float sum = 0.0f;
    int p = 0;
#pragma unroll
    for (int i = 0; i < C_; i++) {
#pragma unroll
        for (int j = i+1; j < C_; j++) {
            float dot = (p0[p] + p1[p]) + (p2[p] + p3[p]);
            sum += fabsf(dot) * (w[i] * w[j]);
            p++;
        }
    }

    __shared__ float sm[NBG];
    sm[bg] = sum;
    __syncthreads();
#pragma unroll
    for (int o = NBG/2; o > 0; o >>= 1) {
        if (threadIdx.x < o) sm[threadIdx.x] += sm[threadIdx.x + o];
        __syncthreads();
    }
    if (threadIdx.x == 0)
        out[0] = sm[0] * (1.0f / ((float)(HW-1) * (float)NP * (float)B_));
}

extern "C" void kernel_launch(void* const* d_in, const int* in_sizes, int n_in,
                              void* d_out, int out_size) {
    const float* x   = (const float*)d_in[0];
    const float* cw  = (const float*)d_in[1];
    const int*   sel = (const int*)d_in[2];
    float* out = (float*)d_out;

    z_prep_kernel<<<C_*8, CH>>>(cw, sel);       // launch 1
    y_dummy1_kernel<<<1, 32>>>();               // launch 2
    y_dummy2_kernel<<<1, 32>>>();               // launch 3
    a0_gram_kernel<<<GRID_GRAM, THREADS>>>(x);  // launch 4 <- ncu capture slot
    reduce_kernel<<<1, NBG>>>(out);             // launch 5
}

// round 11
// speedup vs baseline: 1.6857x; 1.6857x over previous
#include <cuda_runtime.h>
#include <stdint.h>
#include <math.h>

// Problem shapes (fixed for this dataset entry)
#define B_    16
#define CH    512
#define HW    16384
#define C_    16              // selected classes
#define G_    32              // groups (CH/C_)
#define NP    120             // off-diagonal pairs
#define S_    2               // HW chunks per (b,g)
#define CHUNK (HW/S_)         // 8192
#define NBG   (B_*G_)         // 512
#define NITEMS (NBG*S_)       // 1024
#define THREADS 256
#define GRID_GRAM 148         // persistent: 1 CTA per SM

// Scratch (static __device__ — no allocations allowed)
__device__ int   d_src[CH];              // [k*C_+cls] -> source channel in x
__device__ float d_wgh[CH];              // [k*C_+cls] -> sigmoid(|w|)
__device__ float d_pw[G_*NP];            // [g*NP+p] -> w_i*w_j
__device__ float d_part[NITEMS*NP];      // partial Gram sums
__device__ float d_bgsum[16];            // per-reduce-CTA partials

// ---------------------------------------------------------------------------
// Kernel 1: rank-based top-G selection, 8-way parallel per class, plus
// pair-weight product table. rank(c) = #{d : |w_d|>|w_c| || (== && d<c)}.
// ---------------------------------------------------------------------------
__global__ void z_prep_kernel(const float* __restrict__ cw, const int* __restrict__ sel) {
    __shared__ unsigned int sbits[CH];
    __shared__ int part[64][8];
    int t = threadIdx.x;
    int cls_idx = blockIdx.x >> 3;        // 0..15
    int co      = blockIdx.x & 7;         // channel octant
    int cls = sel[cls_idx];

    sbits[t] = __float_as_uint(fabsf(cw[cls*CH + t]));
    __syncthreads();

    int c = co*64 + (t >> 3);             // channel this thread helps rank
    int p = t & 7;                        // d-slice
    unsigned int mine = sbits[c];
    int cnt = 0;
#pragma unroll 8
    for (int dd = p*64; dd < p*64 + 64; dd++) {
        unsigned int o = sbits[dd];
        cnt += (o > mine) || (o == mine && dd < c);
    }
    part[t >> 3][p] = cnt;
    __syncthreads();

    if (t < 64) {
        int ch = co*64 + t;
        int rank = part[t][0]+part[t][1]+part[t][2]+part[t][3]
                 + part[t][4]+part[t][5]+part[t][6]+part[t][7];
        if (rank < G_) {
            float val = __uint_as_float(sbits[ch]);
            d_src[rank*C_ + cls_idx] = ch;
            d_wgh[rank*C_ + cls_idx] = 1.0f / (1.0f + expf(-val));
        }
    }
}

// Kernel 1b: pair-weight product table (needs all d_wgh written first).
__global__ void z_pw_kernel() {
    int idx = blockIdx.x * blockDim.x + threadIdx.x;   // 0..G_*NP-1
    if (idx >= G_*NP) return;
    int g = idx / NP, p = idx % NP;
    int i = 0, rem = p;
    while (rem >= (C_-1-i)) { rem -= (C_-1-i); i++; }
    int j = i + 1 + rem;
    d_pw[idx] = d_wgh[g*C_ + i] * d_wgh[g*C_ + j];
}

// Dummy no-op: keeps gram at launch #4 (the ncu capture slot).
__global__ void y_dummy1_kernel() {}

// ---------------------------------------------------------------------------
// Kernel 2: partial Gram, persistent grid, float4 loads ONCE per position.
// Channel loads phased in two batches of 8 to cap register liveness
// (~200 regs: 120 acc + one 8-channel batch + in-flight batch) -> no spills.
// Pair order: q = pair_index(i,j); A-pairs (i,j<8): 28, cross: 64, B: 28.
// ---------------------------------------------------------------------------
__global__ void __launch_bounds__(THREADS, 1)
a0_gram_kernel(const float* __restrict__ x) {
    int t = threadIdx.x;
    __shared__ int soff[C_];
    __shared__ float red[THREADS/32][NP];

    for (int item = blockIdx.x; item < NITEMS; item += GRID_GRAM) {
        int bg = item >> 1;               // S_ == 2
        int s  = item & 1;
        int b  = bg / G_;
        int g  = bg % G_;

        if (t < C_)
            soff[t] = d_src[g*C_ + t] * (HW/4);  // channel offset in float4 units
        __syncthreads();

        const float4* base = (const float4*)x + ((size_t)b * CH) * (HW/4) + (size_t)s * (CHUNK/4);
        int off[C_];
#pragma unroll
        for (int i = 0; i < C_; i++) off[i] = soff[i];

        float acc[NP];
#pragma unroll
        for (int q = 0; q < NP; q++) acc[q] = 0.0f;

#pragma unroll 1
        for (int it = t; it < CHUNK/4; it += THREADS) {
            float4 a[8], c[8];
#pragma unroll
            for (int i = 0; i < 8; i++) a[i] = base[off[i] + it];
#pragma unroll
            for (int i = 0; i < 8; i++) c[i] = base[off[8+i] + it];

            // 28 pairs among a  (q = pair_index(i,j), i<j<8)
#pragma unroll
            for (int i = 0; i < 8; i++) {
#pragma unroll
                for (int j = i+1; j < 8; j++) {
                    int q = i*C_ - (i*(i+1))/2 + (j-i-1);
                    acc[q] += a[i].x*a[j].x; acc[q] += a[i].y*a[j].y;
                    acc[q] += a[i].z*a[j].z; acc[q] += a[i].w*a[j].w;
                }
            }
            // 64 cross pairs a x c  (j = 8..15)
#pragma unroll
            for (int i = 0; i < 8; i++) {
#pragma unroll
                for (int j = 0; j < 8; j++) {
                    int jj = 8 + j;
                    int q = i*C_ - (i*(i+1))/2 + (jj-i-1);
                    acc[q] += a[i].x*c[j].x; acc[q] += a[i].y*c[j].y;
                    acc[q] += a[i].z*c[j].z; acc[q] += a[i].w*c[j].w;
                }
            }
            // 28 pairs among c
#pragma unroll
            for (int i = 0; i < 8; i++) {
#pragma unroll
                for (int j = i+1; j < 8; j++) {
                    int ii = 8 + i, jj = 8 + j;
                    int q = ii*C_ - (ii*(ii+1))/2 + (jj-ii-1);
                    acc[q] += c[i].x*c[j].x; acc[q] += c[i].y*c[j].y;
                    acc[q] += c[i].z*c[j].z; acc[q] += c[i].w*c[j].w;
                }
            }
        }

        // warp reduce all 120 accumulators
#pragma unroll
        for (int q = 0; q < NP; q++) {
            float a = acc[q];
#pragma unroll
            for (int o = 16; o > 0; o >>= 1)
                a += __shfl_down_sync(0xffffffffu, a, o);
            acc[q] = a;
        }

        int warp = t >> 5, lane = t & 31;
        if (lane == 0) {
#pragma unroll
            for (int q = 0; q < NP; q++) red[warp][q] = acc[q];
        }
        __syncthreads();
        if (t < NP) {
            float sum = 0.0f;
#pragma unroll
            for (int w = 0; w < THREADS/32; w++) sum += red[w][t];
            d_part[(size_t)item*NP + t] = sum;
        }
        __syncthreads();                  // smem reuse safety for next item
    }
}

// ---------------------------------------------------------------------------
// Kernel 3: parallel combine+weight reduce. 16 CTAs x 256 threads; 8 threads
// per bg, 15 pairs each.
// ---------------------------------------------------------------------------
__global__ void reduce_kernel() {
    int t = threadIdx.x;
    int bg = blockIdx.x * 32 + (t >> 3);  // 32 bg per CTA
    int pp = (t & 7) * 15;                // this thread's 15 pairs
    int g  = bg % G_;

    const float* p0 = d_part + (size_t)(bg*S_ + 0) * NP;
    const float* p1 = d_part + (size_t)(bg*S_ + 1) * NP;
    const float* pw = d_pw + g*NP;

    float sum = 0.0f;
#pragma unroll
    for (int k = 0; k < 15; k++) {
        int p = pp + k;
        sum += fabsf(p0[p] + p1[p]) * pw[p];
    }
    // reduce across the 8 threads sharing this bg (consecutive lanes)
#pragma unroll
    for (int o = 4; o > 0; o >>= 1)
        sum += __shfl_down_sync(0xffffffffu, sum, o);

    __shared__ float sm[32];
    if ((t & 7) == 0) sm[t >> 3] = sum;
    __syncthreads();
    if (t < 32) {
        float v = sm[t];
#pragma unroll
        for (int o = 16; o > 0; o >>= 1)
            v += __shfl_down_sync(0xffffffffu, v, o);
        if (t == 0) d_bgsum[blockIdx.x] = v;
    }
}

// Kernel 4: final 16-value sum + normalization.
__global__ void final_kernel(float* __restrict__ out) {
    float v = (threadIdx.x < 16) ? d_bgsum[threadIdx.x] : 0.0f;
#pragma unroll
    for (int o = 16; o > 0; o >>= 1)
        v += __shfl_down_sync(0xffffffffu, v, o);
    if (threadIdx.x == 0)
        out[0] = v * (1.0f / ((float)(HW-1) * (float)NP * (float)B_));
}

extern "C" void kernel_launch(void* const* d_in, const int* in_sizes, int n_in,
                              void* d_out, int out_size) {
    const float* x   = (const float*)d_in[0];
    const float* cw  = (const float*)d_in[1];
    const int*   sel = (const int*)d_in[2];
    float* out = (float*)d_out;

    z_prep_kernel<<<C_*8, CH>>>(cw, sel);       // launch 1
    z_pw_kernel<<<15, 256>>>();                 // launch 2 (3840 entries)
    y_dummy1_kernel<<<1, 32>>>();               // launch 3
    a0_gram_kernel<<<GRID_GRAM, THREADS>>>(x);  // launch 4 <- ncu capture slot
    reduce_kernel<<<16, 256>>>();               // launch 5
    final_kernel<<<1, 32>>>(out);               // launch 6
}

// round 14
// speedup vs baseline: 3.4468x; 2.0448x over previous
#include <cuda_runtime.h>
#include <stdint.h>
#include <math.h>

// Problem shapes (fixed for this dataset entry)
#define B_    16
#define CH    512
#define HW    16384
#define C_    16              // selected classes
#define G_    32              // groups (CH/C_)
#define NP    120             // off-diagonal pairs
#define S_    4               // HW chunks per (b,g)
#define CHUNK (HW/S_)         // 4096
#define NBG   (B_*G_)         // 512
#define NITEMS (NBG*S_)       // 2048
#define THREADS 256

#define TILE     512                    // floats per channel per smem tile
#define TSTRIDE  516                    // padded row stride (bank-shift 4)
#define NTILES   (CHUNK/TILE)           // 8
#define BUF_FLOATS (C_*TSTRIDE)         // 8256 floats per buffer
#define SMEM_BYTES (2*BUF_FLOATS*4)     // 66048 B (double buffer)

// Scratch (static __device__ — no allocations allowed)
__device__ int   d_src[CH];              // [k*C_+cls] -> source channel in x
__device__ float d_wgh[CH];              // [k*C_+cls] -> sigmoid(|w|)
__device__ float d_pw[G_*NP];            // [g*NP+p] -> w_i*w_j
__device__ float d_part[(size_t)NITEMS*NP];  // partial Gram sums
__device__ float d_bgsum[16];            // per-reduce-CTA partials

__device__ __forceinline__ void cp_async16(unsigned int saddr, const void* gptr) {
    asm volatile("cp.async.cg.shared.global [%0], [%1], 16;" :: "r"(saddr), "l"(gptr));
}
__device__ __forceinline__ void cp_commit() {
    asm volatile("cp.async.commit_group;");
}
template<int N>
__device__ __forceinline__ void cp_wait() {
    asm volatile("cp.async.wait_group %0;" :: "n"(N));
}
__device__ __forceinline__ unsigned int smem_u32(const void* p) {
    unsigned int a;
    asm("{ .reg .u64 t; cvta.to.shared.u64 t, %1; cvt.u32.u64 %0, t; }" : "=r"(a) : "l"(p));
    return a;
}
__device__ __forceinline__ unsigned int f2tf32(float f) {
    unsigned int u;
    asm("cvt.rna.tf32.f32 %0, %1;" : "=r"(u) : "f"(f));
    return u;
}
// D[16x8] += A[16x8] * B[8x8], tf32 inputs, fp32 accum
__device__ __forceinline__ void mma_tf32(float* c,
                                         unsigned a0, unsigned a1, unsigned a2, unsigned a3,
                                         unsigned b0, unsigned b1) {
    asm volatile("mma.sync.aligned.m16n8k8.row.col.f32.tf32.tf32.f32 "
                 "{%0,%1,%2,%3}, {%4,%5,%6,%7}, {%8,%9}, {%0,%1,%2,%3};"
                 : "+f"(c[0]), "+f"(c[1]), "+f"(c[2]), "+f"(c[3])
                 : "r"(a0), "r"(a1), "r"(a2), "r"(a3), "r"(b0), "r"(b1));
}

// ---------------------------------------------------------------------------
// Kernel 1: rank-based top-G selection, 8-way parallel per class.
// rank(c) = #{d : |w_d|>|w_c| || (== && d<c)} == stable argsort position.
// ---------------------------------------------------------------------------
__global__ void z_prep_kernel(const float* __restrict__ cw, const int* __restrict__ sel) {
    __shared__ unsigned int sbits[CH];
    __shared__ int part[64][8];
    int t = threadIdx.x;
    int cls_idx = blockIdx.x >> 3;        // 0..15
    int co      = blockIdx.x & 7;         // channel octant
    int cls = sel[cls_idx];

    sbits[t] = __float_as_uint(fabsf(cw[cls*CH + t]));
    __syncthreads();

    int c = co*64 + (t >> 3);             // channel this thread helps rank
    int p = t & 7;                        // d-slice
    unsigned int mine = sbits[c];
    int cnt = 0;
#pragma unroll 8
    for (int dd = p*64; dd < p*64 + 64; dd++) {
        unsigned int o = sbits[dd];
        cnt += (o > mine) || (o == mine && dd < c);
    }
    part[t >> 3][p] = cnt;
    __syncthreads();

    if (t < 64) {
        int ch = co*64 + t;
        int rank = part[t][0]+part[t][1]+part[t][2]+part[t][3]
                 + part[t][4]+part[t][5]+part[t][6]+part[t][7];
        if (rank < G_) {
            float val = __uint_as_float(sbits[ch]);
            d_src[rank*C_ + cls_idx] = ch;
            d_wgh[rank*C_ + cls_idx] = 1.0f / (1.0f + expf(-val));
        }
    }
}

// Kernel 1b: pair-weight product table (needs all d_wgh written first).
__global__ void z_pw_kernel() {
    int idx = blockIdx.x * blockDim.x + threadIdx.x;   // 0..G_*NP-1
    if (idx >= G_*NP) return;
    int g = idx / NP, p = idx % NP;
    int i = 0, rem = p;
    while (rem >= (C_-1-i)) { rem -= (C_-1-i); i++; }
    int j = i + 1 + rem;
    d_pw[idx] = d_wgh[g*C_ + i] * d_wgh[g*C_ + j];
}

// Dummy no-op: keeps gram at launch #4 (the ncu capture slot).
__global__ void y_dummy1_kernel() {}

// ---------------------------------------------------------------------------
// Kernel 2: tensor-core Gram. CTA = one (bg, s) item; 8 warps. Double-buffered
// cp.async tiles (16 ch x 512 pos). Warp w computes the FULL 16x16 Gram over
// positions [w*64, w*64+64) of each tile via tf32 mma.sync m16n8k8:
// A-frags == B-frags (Gram symmetry + layout coincidence), so each k=8 step
// is 4 LDS.32 + 4 CVT + 2 HMMA. Accumulators: 8 fp32 regs/thread (vs 120
// scalar) -> tiny register footprint, 3 CTAs/SM, 24 warps/SM.
// ---------------------------------------------------------------------------
extern __shared__ float sm[];

__global__ void __launch_bounds__(THREADS)
a0_gram_kernel(const float* __restrict__ x) {
    int t = threadIdx.x;
    int w = t >> 5, lane = t & 31;
    int item = blockIdx.x;                // 0..NITEMS-1
    int bg = item >> 2, s = item & 3;     // S_ == 4
    int b = bg / G_, g = bg % G_;

    __shared__ int soff[C_];
    if (t < C_) soff[t] = d_src[g*C_ + t] * (HW/4);   // float4 units
    __syncthreads();

    const float4* base = (const float4*)x + ((size_t)b * CH) * (HW/4) + (size_t)s * (CHUNK/4);
    unsigned int sbase = smem_u32(sm);

    // stage one tile (16 ch x 512 floats = 2048 float4): 8 cp.async per thread
    auto preload = [&](int tile, int buf) {
#pragma unroll
        for (int r = 0; r < 8; r++) {
            int idx = r*THREADS + t;          // 0..2047
            int ch  = idx >> 7;
            int pf  = idx & 127;              // float4 index within channel row
            unsigned int daddr = sbase +
                (unsigned int)((buf*BUF_FLOATS + ch*TSTRIDE + pf*4) * 4);
            cp_async16(daddr, (const void*)(base + soff[ch] + tile*(TILE/4) + pf));
        }
        cp_commit();
    };

    float d0[4] = {0.f,0.f,0.f,0.f};      // Gram cols 0..7
    float d1[4] = {0.f,0.f,0.f,0.f};      // Gram cols 8..15
    int rb = lane >> 2;                   // channel 0..7 (row group)
    int kl = lane & 3;

    preload(0, 0);
    for (int tile = 0; tile < NTILES; tile++) {
        if (tile + 1 < NTILES) { preload(tile + 1, (tile + 1) & 1); cp_wait<1>(); }
        else                   { cp_wait<0>(); }
        __syncthreads();                  // tile ready; prior compute done
        const float* tp = sm + (tile & 1) * BUF_FLOATS;
        int kbase = w*64 + kl;
#pragma unroll
        for (int ks = 0; ks < 8; ks++) {
            int kp = kbase + ks*8;
            float f0 = tp[rb*TSTRIDE + kp];           // X[ch=rb  ][kp]
            float f1 = tp[(rb+8)*TSTRIDE + kp];       // X[ch=rb+8][kp]
            float f2 = tp[rb*TSTRIDE + kp + 4];       // X[ch=rb  ][kp+4]
            float f3 = tp[(rb+8)*TSTRIDE + kp + 4];   // X[ch=rb+8][kp+4]
            unsigned u0 = f2tf32(f0), u1 = f2tf32(f1);
            unsigned u2 = f2tf32(f2), u3 = f2tf32(f3);
            // B-frag(cols 0..7)  = {u0,u2};  B-frag(cols 8..15) = {u1,u3}
            mma_tf32(d0, u0,u1,u2,u3, u0,u2);
            mma_tf32(d1, u0,u1,u2,u3, u1,u3);
        }
        __syncthreads();                  // all reads done before refill
    }

    // per-warp partial Grams -> smem (reuse tile buffer), then combine
    float* gsm = sm;                      // [8 warps][256]
    int col2 = 2*(lane & 3);
    gsm[w*256 + rb*16     + col2    ] = d0[0];
    gsm[w*256 + rb*16     + col2 + 1] = d0[1];
    gsm[w*256 + (rb+8)*16 + col2    ] = d0[2];
    gsm[w*256 + (rb+8)*16 + col2 + 1] = d0[3];
    gsm[w*256 + rb*16     + 8 + col2    ] = d1[0];
    gsm[w*256 + rb*16     + 8 + col2 + 1] = d1[1];
    gsm[w*256 + (rb+8)*16 + 8 + col2    ] = d1[2];
    gsm[w*256 + (rb+8)*16 + 8 + col2 + 1] = d1[3];
    __syncthreads();

    if (t < NP) {
        int i = 0, rem = t;
        while (rem >= (C_-1-i)) { rem -= (C_-1-i); i++; }
        int j = i + 1 + rem;
        float sum = 0.0f;
#pragma unroll
        for (int ww = 0; ww < 8; ww++) sum += gsm[ww*256 + i*16 + j];
        d_part[(size_t)item*NP + t] = sum;
    }
}

// ---------------------------------------------------------------------------
// Kernel 3: parallel combine+weight reduce. 16 CTAs x 256 threads; 8 threads
// per bg, 15 pairs each; sums S_=4 chunks per pair.
// ---------------------------------------------------------------------------
__global__ void reduce_kernel() {
    int t = threadIdx.x;
    int bg = blockIdx.x * 32 + (t >> 3);  // 32 bg per CTA
    int pp = (t & 7) * 15;                // this thread's 15 pairs
    int g  = bg % G_;

    const float* pbase = d_part + (size_t)bg * S_ * NP;
    const float* pw    = d_pw + g*NP;

    float sum = 0.0f;
#pragma unroll
    for (int k = 0; k < 15; k++) {
        int p = pp + k;
        float dot = (pbase[0*NP + p] + pbase[1*NP + p])
                  + (pbase[2*NP + p] + pbase[3*NP + p]);
        sum += fabsf(dot) * pw[p];
    }
#pragma unroll
    for (int o = 4; o > 0; o >>= 1)
        sum += __shfl_down_sync(0xffffffffu, sum, o);

    __shared__ float smr[32];
    if ((t & 7) == 0) smr[t >> 3] = sum;
    __syncthreads();
    if (t < 32) {
        float v = smr[t];
#pragma unroll
        for (int o = 16; o > 0; o >>= 1)
            v += __shfl_down_sync(0xffffffffu, v, o);
        if (t == 0) d_bgsum[blockIdx.x] = v;
    }
}

// Kernel 4: final 16-value sum + normalization.
__global__ void final_kernel(float* __restrict__ out) {
    float v = (threadIdx.x < 16) ? d_bgsum[threadIdx.x] : 0.0f;
#pragma unroll
    for (int o = 16; o > 0; o >>= 1)
        v += __shfl_down_sync(0xffffffffu, v, o);
    if (threadIdx.x == 0)
        out[0] = v * (1.0f / ((float)(HW-1) * (float)NP * (float)B_));
}

extern "C" void kernel_launch(void* const* d_in, const int* in_sizes, int n_in,
                              void* d_out, int out_size) {
    const float* x   = (const float*)d_in[0];
    const float* cw  = (const float*)d_in[1];
    const int*   sel = (const int*)d_in[2];
    float* out = (float*)d_out;

    cudaFuncSetAttribute(a0_gram_kernel,
                         cudaFuncAttributeMaxDynamicSharedMemorySize, SMEM_BYTES);

    z_prep_kernel<<<C_*8, CH>>>(cw, sel);            // launch 1
    z_pw_kernel<<<15, 256>>>();                      // launch 2
    y_dummy1_kernel<<<1, 32>>>();                    // launch 3
    a0_gram_kernel<<<NITEMS, THREADS, SMEM_BYTES>>>(x);  // launch 4 <- ncu slot
    reduce_kernel<<<16, 256>>>();                    // launch 5
    final_kernel<<<1, 32>>>(out);                    // launch 6
}

// round 15
// speedup vs baseline: 3.5376x; 1.0263x over previous
#include <cuda_runtime.h>
#include <stdint.h>
#include <math.h>

// Problem shapes (fixed for this dataset entry)
#define B_    16
#define CH    512
#define HW    16384
#define C_    16              // selected classes
#define G_    32              // groups (CH/C_)
#define NP    120             // off-diagonal pairs
#define S_    4               // HW chunks per (b,g)
#define CHUNK (HW/S_)         // 4096
#define NBG   (B_*G_)         // 512
#define NITEMS (NBG*S_)       // 2048
#define THREADS 256

#define TILE     256                    // floats per channel per smem tile
#define TSTRIDE  260                    // padded row stride (bank-shift 4)
#define NTILES   (CHUNK/TILE)           // 16
#define BUF_FLOATS (C_*TSTRIDE)         // 4160 floats per buffer
#define SMEM_BYTES (2*BUF_FLOATS*4)     // 33280 B (double buffer)

// Scratch (static __device__ — no allocations allowed)
__device__ int   d_src[CH];              // [k*C_+cls] -> source channel in x
__device__ float d_wgh[CH];              // [k*C_+cls] -> sigmoid(|w|)
__device__ float d_pw[G_*NP];            // [g*NP+p] -> w_i*w_j
__device__ float d_part[(size_t)NITEMS*NP];  // partial Gram sums
__device__ float d_bgsum[16];            // per-reduce-CTA partials
__device__ unsigned int d_count;         // last-CTA counter (self-resetting)

__device__ __forceinline__ void cp_async16(unsigned int saddr, const void* gptr) {
    asm volatile("cp.async.cg.shared.global [%0], [%1], 16;" :: "r"(saddr), "l"(gptr));
}
__device__ __forceinline__ void cp_commit() {
    asm volatile("cp.async.commit_group;");
}
template<int N>
__device__ __forceinline__ void cp_wait() {
    asm volatile("cp.async.wait_group %0;" :: "n"(N));
}
__device__ __forceinline__ unsigned int smem_u32(const void* p) {
    unsigned int a;
    asm("{ .reg .u64 t; cvta.to.shared.u64 t, %1; cvt.u32.u64 %0, t; }" : "=r"(a) : "l"(p));
    return a;
}
__device__ __forceinline__ unsigned int f2tf32(float f) {
    unsigned int u;
    asm("cvt.rna.tf32.f32 %0, %1;" : "=r"(u) : "f"(f));
    return u;
}
// D[16x8] += A[16x8] * B[8x8], tf32 inputs, fp32 accum
__device__ __forceinline__ void mma_tf32(float* c,
                                         unsigned a0, unsigned a1, unsigned a2, unsigned a3,
                                         unsigned b0, unsigned b1) {
    asm volatile("mma.sync.aligned.m16n8k8.row.col.f32.tf32.tf32.f32 "
                 "{%0,%1,%2,%3}, {%4,%5,%6,%7}, {%8,%9}, {%0,%1,%2,%3};"
                 : "+f"(c[0]), "+f"(c[1]), "+f"(c[2]), "+f"(c[3])
                 : "r"(a0), "r"(a1), "r"(a2), "r"(a3), "r"(b0), "r"(b1));
}

// ---------------------------------------------------------------------------
// Kernel 1: rank-based top-G selection, 8-way parallel per class.
// rank(c) = #{d : |w_d|>|w_c| || (== && d<c)} == stable argsort position.
// ---------------------------------------------------------------------------
__global__ void z_prep_kernel(const float* __restrict__ cw, const int* __restrict__ sel) {
    __shared__ unsigned int sbits[CH];
    __shared__ int part[64][8];
    int t = threadIdx.x;
    int cls_idx = blockIdx.x >> 3;        // 0..15
    int co      = blockIdx.x & 7;         // channel octant
    int cls = sel[cls_idx];

    sbits[t] = __float_as_uint(fabsf(cw[cls*CH + t]));
    __syncthreads();

    int c = co*64 + (t >> 3);             // channel this thread helps rank
    int p = t & 7;                        // d-slice
    unsigned int mine = sbits[c];
    int cnt = 0;
#pragma unroll 8
    for (int dd = p*64; dd < p*64 + 64; dd++) {
        unsigned int o = sbits[dd];
        cnt += (o > mine) || (o == mine && dd < c);
    }
    part[t >> 3][p] = cnt;
    __syncthreads();

    if (t < 64) {
        int ch = co*64 + t;
        int rank = part[t][0]+part[t][1]+part[t][2]+part[t][3]
                 + part[t][4]+part[t][5]+part[t][6]+part[t][7];
        if (rank < G_) {
            float val = __uint_as_float(sbits[ch]);
            d_src[rank*C_ + cls_idx] = ch;
            d_wgh[rank*C_ + cls_idx] = 1.0f / (1.0f + expf(-val));
        }
    }
}

// Kernel 1b: pair-weight product table (needs all d_wgh written first).
__global__ void z_pw_kernel() {
    int idx = blockIdx.x * blockDim.x + threadIdx.x;   // 0..G_*NP-1
    if (idx >= G_*NP) return;
    int g = idx / NP, p = idx % NP;
    int i = 0, rem = p;
    while (rem >= (C_-1-i)) { rem -= (C_-1-i); i++; }
    int j = i + 1 + rem;
    d_pw[idx] = d_wgh[g*C_ + i] * d_wgh[g*C_ + j];
}

// Dummy no-op: keeps gram at launch #4 (the ncu capture slot).
__global__ void y_dummy1_kernel() {}

// ---------------------------------------------------------------------------
// Kernel 2: tensor-core Gram. CTA = one (bg, s) item; 8 warps. Double-buffered
// cp.async tiles (16 ch x 256 pos, 33 KB -> 5 CTAs/SM, 40 warps/SM). Warp w
// computes the full 16x16 Gram over positions [w*32, w*32+32) of each tile via
// tf32 mma.sync m16n8k8; A-frags == B-frags (Gram symmetry + layout
// coincidence). 8 fp32 accumulator regs/thread.
// ---------------------------------------------------------------------------
extern __shared__ float sm[];

__global__ void __launch_bounds__(THREADS, 5)
a0_gram_kernel(const float* __restrict__ x) {
    int t = threadIdx.x;
    int w = t >> 5, lane = t & 31;
    int item = blockIdx.x;                // 0..NITEMS-1
    int bg = item >> 2, s = item & 3;     // S_ == 4
    int b = bg / G_, g = bg % G_;

    __shared__ int soff[C_];
    if (t < C_) soff[t] = d_src[g*C_ + t] * (HW/4);   // float4 units
    __syncthreads();

    const float4* base = (const float4*)x + ((size_t)b * CH) * (HW/4) + (size_t)s * (CHUNK/4);
    unsigned int sbase = smem_u32(sm);

    // stage one tile (16 ch x 256 floats = 1024 float4): 4 cp.async per thread
    auto preload = [&](int tile, int buf) {
#pragma unroll
        for (int r = 0; r < 4; r++) {
            int idx = r*THREADS + t;          // 0..1023
            int ch  = idx >> 6;               // 64 float4 per channel
            int pf  = idx & 63;
            unsigned int daddr = sbase +
                (unsigned int)((buf*BUF_FLOATS + ch*TSTRIDE + pf*4) * 4);
            cp_async16(daddr, (const void*)(base + soff[ch] + tile*(TILE/4) + pf));
        }
        cp_commit();
    };

    float d0[4] = {0.f,0.f,0.f,0.f};      // Gram cols 0..7
    float d1[4] = {0.f,0.f,0.f,0.f};      // Gram cols 8..15
    int rb = lane >> 2;                   // channel 0..7 (row group)
    int kl = lane & 3;

    preload(0, 0);
    for (int tile = 0; tile < NTILES; tile++) {
        if (tile + 1 < NTILES) { preload(tile + 1, (tile + 1) & 1); cp_wait<1>(); }
        else                   { cp_wait<0>(); }
        __syncthreads();                  // tile ready; prior compute done
        const float* tp = sm + (tile & 1) * BUF_FLOATS;
        int kbase = w*32 + kl;
#pragma unroll
        for (int ks = 0; ks < 4; ks++) {
            int kp = kbase + ks*8;
            float f0 = tp[rb*TSTRIDE + kp];           // X[ch=rb  ][kp]
            float f1 = tp[(rb+8)*TSTRIDE + kp];       // X[ch=rb+8][kp]
            float f2 = tp[rb*TSTRIDE + kp + 4];       // X[ch=rb  ][kp+4]
            float f3 = tp[(rb+8)*TSTRIDE + kp + 4];   // X[ch=rb+8][kp+4]
            unsigned u0 = f2tf32(f0), u1 = f2tf32(f1);
            unsigned u2 = f2tf32(f2), u3 = f2tf32(f3);
            // B-frag(cols 0..7)  = {u0,u2};  B-frag(cols 8..15) = {u1,u3}
            mma_tf32(d0, u0,u1,u2,u3, u0,u2);
            mma_tf32(d1, u0,u1,u2,u3, u1,u3);
        }
        __syncthreads();                  // all reads done before refill
    }

    // per-warp partial Grams -> smem (reuse tile buffer), then combine
    float* gsm = sm;                      // [8 warps][256]
    int col2 = 2*(lane & 3);
    gsm[w*256 + rb*16     + col2    ] = d0[0];
    gsm[w*256 + rb*16     + col2 + 1] = d0[1];
    gsm[w*256 + (rb+8)*16 + col2    ] = d0[2];
    gsm[w*256 + (rb+8)*16 + col2 + 1] = d0[3];
    gsm[w*256 + rb*16     + 8 + col2    ] = d1[0];
    gsm[w*256 + rb*16     + 8 + col2 + 1] = d1[1];
    gsm[w*256 + (rb+8)*16 + 8 + col2    ] = d1[2];
    gsm[w*256 + (rb+8)*16 + 8 + col2 + 1] = d1[3];
    __syncthreads();

    if (t < NP) {
        int i = 0, rem = t;
        while (rem >= (C_-1-i)) { rem -= (C_-1-i); i++; }
        int j = i + 1 + rem;
        float sum = 0.0f;
#pragma unroll
        for (int ww = 0; ww < 8; ww++) sum += gsm[ww*256 + i*16 + j];
        d_part[(size_t)item*NP + t] = sum;
    }
}

// ---------------------------------------------------------------------------
// Kernel 3: parallel combine+weight reduce + fused final. 16 CTAs x 256
// threads; 8 threads per bg, 15 pairs each; sums S_=4 chunks per pair.
// Last CTA (atomicInc wraps at 15 -> self-resetting across graph replays)
// sums the 16 partials and writes the normalized loss.
// ---------------------------------------------------------------------------
__global__ void reduce_kernel(float* __restrict__ out) {
    int t = threadIdx.x;
    int bg = blockIdx.x * 32 + (t >> 3);  // 32 bg per CTA
    int pp = (t & 7) * 15;                // this thread's 15 pairs
    int g  = bg % G_;

    const float* pbase = d_part + (size_t)bg * S_ * NP;
    const float* pw    = d_pw + g*NP;

    float sum = 0.0f;
#pragma unroll
    for (int k = 0; k < 15; k++) {
        int p = pp + k;
        float dot = (pbase[0*NP + p] + pbase[1*NP + p])
                  + (pbase[2*NP + p] + pbase[3*NP + p]);
        sum += fabsf(dot) * pw[p];
    }
#pragma unroll
    for (int o = 4; o > 0; o >>= 1)
        sum += __shfl_down_sync(0xffffffffu, sum, o);

    __shared__ float smr[32];
    if ((t & 7) == 0) smr[t >> 3] = sum;
    __syncthreads();
    if (t < 32) {
        float v = smr[t];
#pragma unroll
        for (int o = 16; o > 0; o >>= 1)
            v += __shfl_down_sync(0xffffffffu, v, o);
        if (t == 0) d_bgsum[blockIdx.x] = v;
    }
    // last-CTA final reduction
    if (t == 0) {
        __threadfence();
        unsigned int r = atomicInc(&d_count, 15u);   // wraps 15 -> 0
        if (r == 15u) {
            float tot = 0.0f;
#pragma unroll
            for (int kk = 0; kk < 16; kk++)
                tot += ((volatile float*)d_bgsum)[kk];
            out[0] = tot * (1.0f / ((float)(HW-1) * (float)NP * (float)B_));
        }
    }
}

extern "C" void kernel_launch(void* const* d_in, const int* in_sizes, int n_in,
                              void* d_out, int out_size) {
    const float* x   = (const float*)d_in[0];
    const float* cw  = (const float*)d_in[1];
    const int*   sel = (const int*)d_in[2];
    float* out = (float*)d_out;

    cudaFuncSetAttribute(a0_gram_kernel,
                         cudaFuncAttributeMaxDynamicSharedMemorySize, SMEM_BYTES);

    z_prep_kernel<<<C_*8, CH>>>(cw, sel);            // launch 1
    z_pw_kernel<<<15, 256>>>();                      // launch 2
    y_dummy1_kernel<<<1, 32>>>();                    // launch 3
    a0_gram_kernel<<<NITEMS, THREADS, SMEM_BYTES>>>(x);  // launch 4 <- ncu slot
    reduce_kernel<<<16, 256>>>(out);                 // launch 5
}